// round 14
// baseline (speedup 1.0000x reference)
#include <cuda_runtime.h>
#include <cuda_bf16.h>
#include <math.h>
#include <stdint.h>

#define B_ 4
#define S_ 1024
#define D_ 1024
#define H_ 16
#define M_ 4
#define R_ 64
#define DH_ 64
#define EPS_ 1e-8f

// ---------------- scratch (static device globals; no allocation) ----------------
__device__ __align__(16) float g_q[B_ * S_ * D_];
__device__ __align__(16) float g_k[B_ * S_ * D_];
__device__ __align__(16) float g_v[B_ * S_ * D_];
__device__ __align__(16) float g_lm[M_ * S_ * S_];
__device__ __align__(16) float g_gath[M_ * S_ * S_];
__device__ __align__(16) float g_ssq[B_ * H_];
__device__ int g_cnt[B_ * H_];
// FRAGMENT-MAJOR packed bf16x2 hi/lo operands for proj.
__device__ __align__(16) uint32_t g_xh[B_ * S_ * (D_ / 2)];
__device__ __align__(16) uint32_t g_xl[B_ * S_ * (D_ / 2)];
__device__ __align__(16) uint32_t g_wh[3 * D_ * (D_ / 2)];
__device__ __align__(16) uint32_t g_wl[3 * D_ * (D_ / 2)];

// ---------------- helpers ----------------
__device__ __forceinline__ uint32_t f2tf(float x) {
    uint32_t u;
    asm("cvt.rna.tf32.f32 %0, %1;" : "=r"(u) : "f"(x));
    return u;
}
__device__ __forceinline__ float tfbit(float x) { return __uint_as_float(f2tf(x)); }

__device__ __forceinline__ void mma8(float d[4], const uint32_t a[4], const uint32_t b[2]) {
    asm volatile(
        "mma.sync.aligned.m16n8k8.row.col.f32.tf32.tf32.f32 "
        "{%0,%1,%2,%3},{%4,%5,%6,%7},{%8,%9},{%0,%1,%2,%3};"
        : "+f"(d[0]), "+f"(d[1]), "+f"(d[2]), "+f"(d[3])
        : "r"(a[0]), "r"(a[1]), "r"(a[2]), "r"(a[3]), "r"(b[0]), "r"(b[1]));
}

__device__ __forceinline__ void mma16(float d[4], const uint32_t a[4], const uint32_t b[2]) {
    asm volatile(
        "mma.sync.aligned.m16n8k16.row.col.f32.bf16.bf16.f32 "
        "{%0,%1,%2,%3},{%4,%5,%6,%7},{%8,%9},{%0,%1,%2,%3};"
        : "+f"(d[0]), "+f"(d[1]), "+f"(d[2]), "+f"(d[3])
        : "r"(a[0]), "r"(a[1]), "r"(a[2]), "r"(a[3]), "r"(b[0]), "r"(b[1]));
}

__device__ __forceinline__ uint32_t bf2bits(__nv_bfloat162 h) {
    return *(uint32_t*)&h;
}

__device__ __forceinline__ void cpa16(void* dst, const void* src) {
    uint32_t d = (uint32_t)__cvta_generic_to_shared(dst);
    asm volatile("cp.async.cg.shared.global [%0], [%1], 16;" :: "r"(d), "l"(src));
}

// split float2 -> packed bf16x2 hi + lo
__device__ __forceinline__ void split2(float2 f, uint32_t& hi, uint32_t& lo) {
    __nv_bfloat162 h = __floats2bfloat162_rn(f.x, f.y);
    float2 hf = __bfloat1622float2(h);
    __nv_bfloat162 l = __floats2bfloat162_rn(f.x - hf.x, f.y - hf.y);
    hi = bf2bits(h);
    lo = bf2bits(l);
}

// ---------------- prep: fp32 -> fragment-major bf16x2 hi/lo ----------------
__global__ __launch_bounds__(256) void prep_xf(const float* __restrict__ X) {
    int id = blockIdx.x * 256 + threadIdx.x;  // 524288 ids
    int l = id & 31;
    int c = (id >> 5) & 63;
    int g = id >> 11;
    int rr = l >> 2, jj = l & 3;
    const float* r0 = X + (size_t)(g * 16 + rr) * D_ + c * 16 + jj * 2;
    const float* r1 = r0 + 8 * D_;
    float2 f0 = *(const float2*)r0;
    float2 f1 = *(const float2*)r1;
    float2 f2 = *(const float2*)(r0 + 8);
    float2 f3 = *(const float2*)(r1 + 8);
    uint4 hi, lo;
    split2(f0, hi.x, lo.x);
    split2(f1, hi.y, lo.y);
    split2(f2, hi.z, lo.z);
    split2(f3, hi.w, lo.w);
    *(uint4*)&g_xh[(size_t)id * 4] = hi;
    *(uint4*)&g_xl[(size_t)id * 4] = lo;
}

__global__ __launch_bounds__(256) void prep_wf(const float* __restrict__ q,
                                               const float* __restrict__ k,
                                               const float* __restrict__ v) {
    int z = blockIdx.y;
    const float* W = (z == 0) ? q : (z == 1) ? k : v;
    size_t zoff = (size_t)z * D_ * (D_ / 2);
    int id = blockIdx.x * 256 + threadIdx.x;  // 262144 ids
    int l = id & 31;
    int c = (id >> 5) & 63;
    int gN = id >> 11;
    int rr = l >> 2, jj = l & 3;
    const float* w0 = W + (size_t)(gN * 8 + rr) * D_ + c * 16 + jj * 2;
    float2 f0 = *(const float2*)w0;
    float2 f1 = *(const float2*)(w0 + 8);
    uint2 hi, lo;
    split2(f0, hi.x, lo.x);
    split2(f1, hi.y, lo.y);
    *(uint2*)&g_wh[zoff + (size_t)id * 2] = hi;
    *(uint2*)&g_wl[zoff + (size_t)id * 2] = lo;
}

// ---------------- projection GEMM (bf16x3, smem-free, fragment LDG) ----------------
// grid (8, 32, 3); 256 threads, warps 4(m) x 2(n), warp tile 32x64.
// Outputs rounded to tf32 bit patterns (attn consumes as tf32).
__global__ __launch_bounds__(256, 2) void proj_kernel(const float* __restrict__ bq,
                                                      const float* __restrict__ bk,
                                                      const float* __restrict__ bv) {
    const int z = blockIdx.z;
    const float* bias = (z == 0) ? bq : (z == 1) ? bk : bv;
    float* Y = (z == 0) ? g_q : (z == 1) ? g_k : g_v;

    const uint4* fah = (const uint4*)g_xh;
    const uint4* fal = (const uint4*)g_xl;
    const uint2* fbh = (const uint2*)(g_wh + (size_t)z * D_ * (D_ / 2));
    const uint2* fbl = (const uint2*)(g_wl + (size_t)z * D_ * (D_ / 2));

    const int tid = threadIdx.x;
    const int warp = tid >> 5, lane = tid & 31;
    const int gid = lane >> 2, tig = lane & 3;
    const int wm = warp >> 1, wn = warp & 1;
    const int gm0 = blockIdx.y * 8 + wm * 2;
    const int gn0 = blockIdx.x * 16 + wn * 8;

    float acc[2][8][4];
#pragma unroll
    for (int mt = 0; mt < 2; mt++)
#pragma unroll
        for (int nt = 0; nt < 8; nt++)
#pragma unroll
            for (int r = 0; r < 4; r++) acc[mt][nt][r] = 0.f;

#pragma unroll 2
    for (int c = 0; c < 64; c++) {
        uint4 ah[2], al[2];
        ah[0] = fah[((size_t)gm0 * 64 + c) * 32 + lane];
        ah[1] = fah[((size_t)(gm0 + 1) * 64 + c) * 32 + lane];
        al[0] = fal[((size_t)gm0 * 64 + c) * 32 + lane];
        al[1] = fal[((size_t)(gm0 + 1) * 64 + c) * 32 + lane];
#pragma unroll
        for (int nt = 0; nt < 8; nt++) {
            uint2 bh2 = fbh[((size_t)(gn0 + nt) * 64 + c) * 32 + lane];
            uint2 bl2 = fbl[((size_t)(gn0 + nt) * 64 + c) * 32 + lane];
            uint32_t bh[2] = {bh2.x, bh2.y};
            uint32_t bl[2] = {bl2.x, bl2.y};
#pragma unroll
            for (int mt = 0; mt < 2; mt++) {
                mma16(acc[mt][nt], (const uint32_t*)&ah[mt], bh);
                mma16(acc[mt][nt], (const uint32_t*)&al[mt], bh);
                mma16(acc[mt][nt], (const uint32_t*)&ah[mt], bl);
            }
        }
    }
    const int row0 = blockIdx.y * 128;
    const int col0 = blockIdx.x * 128;
#pragma unroll
    for (int mt = 0; mt < 2; mt++) {
        int rg = row0 + wm * 32 + mt * 16 + gid;
#pragma unroll
        for (int nt = 0; nt < 8; nt++) {
            int cg = col0 + wn * 64 + nt * 8 + 2 * tig;
            float bx = bias[cg], by = bias[cg + 1];
            *(float2*)&Y[(size_t)rg * D_ + cg] =
                make_float2(tfbit(acc[mt][nt][0] + bx), tfbit(acc[mt][nt][1] + by));
            *(float2*)&Y[(size_t)(rg + 8) * D_ + cg] =
                make_float2(tfbit(acc[mt][nt][2] + bx), tfbit(acc[mt][nt][3] + by));
        }
    }
}

// ---------------- lm[m,s,t] = sum_r mask1[m,r,s] * mask2[m,r,t] (fp32) ----------------
__global__ __launch_bounds__(256) void lm_kernel(const float* __restrict__ m1,
                                                 const float* __restrict__ m2) {
    __shared__ float As[16][64];
    __shared__ float Bs[16][64];
    const int m = blockIdx.z;
    const int s0 = blockIdx.y * 64, t0 = blockIdx.x * 64;
    const int tid = threadIdx.x;
    const int tx = tid & 15, ty = tid >> 4;
    float acc[4][4];
#pragma unroll
    for (int i = 0; i < 4; i++)
#pragma unroll
        for (int j = 0; j < 4; j++) acc[i][j] = 0.f;

    for (int r0 = 0; r0 < R_; r0 += 16) {
        int rr = tid >> 4, cc = (tid & 15) << 2;
        *(float4*)&As[rr][cc] = *(const float4*)&m1[(size_t)((m * R_ + r0 + rr)) * S_ + s0 + cc];
        *(float4*)&Bs[rr][cc] = *(const float4*)&m2[(size_t)((m * R_ + r0 + rr)) * S_ + t0 + cc];
        __syncthreads();
#pragma unroll
        for (int r = 0; r < 16; r++) {
            float a[4], bb[4];
#pragma unroll
            for (int i = 0; i < 4; i++) a[i] = As[r][ty * 4 + i];
#pragma unroll
            for (int j = 0; j < 4; j++) bb[j] = Bs[r][tx + 16 * j];
#pragma unroll
            for (int i = 0; i < 4; i++)
#pragma unroll
                for (int j = 0; j < 4; j++) acc[i][j] += a[i] * bb[j];
        }
        __syncthreads();
    }
#pragma unroll
    for (int i = 0; i < 4; i++)
#pragma unroll
        for (int j = 0; j < 4; j++)
            g_lm[(size_t)(m * S_ + s0 + ty * 4 + i) * S_ + t0 + tx + 16 * j] = acc[i][j];
}

// ---------------- gathered[m,s,t] = lm[m,s,rb[m,s,t]]  (+ zero ssq/cnt) ----------------
__global__ __launch_bounds__(256) void gather_kernel(const int* __restrict__ rb) {
    if (blockIdx.x == 0 && threadIdx.x < B_ * H_) {
        g_ssq[threadIdx.x] = 0.f;
        g_cnt[threadIdx.x] = 0;
    }
    int i4 = (blockIdx.x * 256 + threadIdx.x) * 4;  // over M*S*S
    int row = i4 >> 10;                             // combined (m*S + s)
    const float* lrow = &g_lm[(size_t)row << 10];
    int4 u = *(const int4*)&rb[i4];
    g_gath[i4 + 0] = lrow[u.x & (S_ - 1)];
    g_gath[i4 + 1] = lrow[u.y & (S_ - 1)];
    g_gath[i4 + 2] = lrow[u.z & (S_ - 1)];
    g_gath[i4 + 3] = lrow[u.w & (S_ - 1)];
}

// ---------------- fused attention (cp.async double-buffered 64-row t-tiles) ----------------
// grid (S/128=8, B*H), 256 thr (8 warps, warp tile m=16). q/k/v already tf32-rounded.
// LAST of the 8 blocks per (b,h) applies the Frobenius scale (threadfence reduction).
#define KSTRIDE 76
#define VSTRIDE 72
#define ATT_BUF_FLOATS (64 * KSTRIDE + 64 * VSTRIDE)
#define ATT_SMEM_BYTES (2 * ATT_BUF_FLOATS * 4)

__global__ __launch_bounds__(256, 2) void attn_kernel(float* __restrict__ out) {
    extern __shared__ float sm[];
    __shared__ int s_last;

    const int tid = threadIdx.x, warp = tid >> 5, lane = tid & 31;
    const int gid = lane >> 2, tig = lane & 3;
    const int bh = blockIdx.y;
    const int b = bh >> 4, h = bh & 15;
    const int midx = h & 3;
    const int s0 = blockIdx.x * 128;
    const int mrow = warp * 16;

    const float* Qg = g_q + (size_t)b * S_ * D_ + h * 64;
    const float* Kg = g_k + (size_t)b * S_ * D_ + h * 64;
    const float* Vg = g_v + (size_t)b * S_ * D_ + h * 64;
    const float* grow = g_gath + (size_t)midx * S_ * S_;

    // Q fragments direct from gmem (values are tf32 bit patterns already)
    uint32_t qf[8][4];
    {
        const float* Qr0 = &Qg[(size_t)(s0 + mrow + gid) * D_];
        const float* Qr1 = &Qg[(size_t)(s0 + mrow + gid + 8) * D_];
#pragma unroll
        for (int kc = 0; kc < 8; kc++) {
            qf[kc][0] = __float_as_uint(Qr0[kc * 8 + tig]);
            qf[kc][1] = __float_as_uint(Qr1[kc * 8 + tig]);
            qf[kc][2] = __float_as_uint(Qr0[kc * 8 + tig + 4]);
            qf[kc][3] = __float_as_uint(Qr1[kc * 8 + tig + 4]);
        }
    }

    float oacc[8][4];
#pragma unroll
    for (int nt = 0; nt < 8; nt++)
#pragma unroll
        for (int r = 0; r < 4; r++) oacc[nt][r] = 0.f;
    float ssq = 0.f;

    const int srcA = (lane & ~3) | (tig >> 1);
    const int srcB = srcA + 2;
    const bool odd = (tig & 1);

    auto stage = [&](int tt) {
        const int t0 = tt * 64;
        float* base = sm + (tt & 1) * ATT_BUF_FLOATS;
#pragma unroll
        for (int t = 0; t < 4; t++) {
            int id = tid + t * 256;
            int r = id >> 4, c = (id & 15) << 2;
            cpa16(&base[r * KSTRIDE + c], &Kg[(size_t)(t0 + r) * D_ + c]);
            cpa16(&base[64 * KSTRIDE + r * VSTRIDE + c], &Vg[(size_t)(t0 + r) * D_ + c]);
        }
        asm volatile("cp.async.commit_group;");
    };

    stage(0);

    for (int tt = 0; tt < 16; tt++) {
        if (tt < 15) {
            stage(tt + 1);
            asm volatile("cp.async.wait_group 1;");
        } else {
            asm volatile("cp.async.wait_group 0;");
        }
        __syncthreads();

        const float* Ks = sm + (tt & 1) * ATT_BUF_FLOATS;
        const float* Vs = Ks + 64 * KSTRIDE;
        const int t0 = tt * 64;

#pragma unroll
        for (int nt = 0; nt < 8; nt++) {
            float p[4] = {0.f, 0.f, 0.f, 0.f};
#pragma unroll
            for (int kc = 0; kc < 8; kc++) {
                uint32_t bf[2];
                bf[0] = __float_as_uint(Ks[(nt * 8 + gid) * KSTRIDE + kc * 8 + tig]);
                bf[1] = __float_as_uint(Ks[(nt * 8 + gid) * KSTRIDE + kc * 8 + tig + 4]);
                mma8(p, qf[kc], bf);
            }
            int srow = s0 + mrow + gid;
            int tcol = t0 + nt * 8 + 2 * tig;
            float2 g0 = *(const float2*)&grow[(size_t)srow * S_ + tcol];
            float2 g1 = *(const float2*)&grow[(size_t)(srow + 8) * S_ + tcol];
            float v0 = p[0] * 0.125f * g0.x;
            float v1 = p[1] * 0.125f * g0.y;
            float v2 = p[2] * 0.125f * g1.x;
            float v3 = p[3] * 0.125f * g1.y;
            ssq += v0 * v0 + v1 * v1 + v2 * v2 + v3 * v3;
            float c0 = tfbit(v0), c1 = tfbit(v1), c2 = tfbit(v2), c3 = tfbit(v3);
            float w00 = __shfl_sync(0xffffffffu, c0, srcA);
            float w01 = __shfl_sync(0xffffffffu, c1, srcA);
            float w10 = __shfl_sync(0xffffffffu, c2, srcA);
            float w11 = __shfl_sync(0xffffffffu, c3, srcA);
            float w20 = __shfl_sync(0xffffffffu, c0, srcB);
            float w21 = __shfl_sync(0xffffffffu, c1, srcB);
            float w30 = __shfl_sync(0xffffffffu, c2, srcB);
            float w31 = __shfl_sync(0xffffffffu, c3, srcB);
            uint32_t af[4];
            af[0] = __float_as_uint(odd ? w01 : w00);
            af[1] = __float_as_uint(odd ? w11 : w10);
            af[2] = __float_as_uint(odd ? w21 : w20);
            af[3] = __float_as_uint(odd ? w31 : w30);
#pragma unroll
            for (int vn = 0; vn < 8; vn++) {
                uint32_t bf[2];
                bf[0] = __float_as_uint(Vs[(nt * 8 + tig) * VSTRIDE + vn * 8 + gid]);
                bf[1] = __float_as_uint(Vs[(nt * 8 + tig + 4) * VSTRIDE + vn * 8 + gid]);
                mma8(oacc[vn], af, bf);
            }
        }
        __syncthreads();
    }

    float* Og = out + (size_t)b * S_ * D_ + h * 64;
    const int srow = s0 + mrow + gid;
#pragma unroll
    for (int nt = 0; nt < 8; nt++) {
        int c = nt * 8 + 2 * tig;
        *(float2*)&Og[(size_t)srow * D_ + c] = make_float2(oacc[nt][0], oacc[nt][1]);
        *(float2*)&Og[(size_t)(srow + 8) * D_ + c] = make_float2(oacc[nt][2], oacc[nt][3]);
    }
#pragma unroll
    for (int off = 16; off; off >>= 1) ssq += __shfl_xor_sync(0xffffffffu, ssq, off);
    if (lane == 0) atomicAdd(&g_ssq[bh], ssq);

    // ---- last of gridDim.x blocks per (b,h) applies Frobenius normalization ----
    __threadfence();
    __syncthreads();
    if (tid == 0)
        s_last = (atomicAdd(&g_cnt[bh], 1) == (int)gridDim.x - 1) ? 1 : 0;
    __syncthreads();
    if (s_last) {
        float f = 1.f / (sqrtf(g_ssq[bh]) + EPS_);
        // scale out[b][:, h*64:(h+1)*64]: 1024 rows x 16 float4
#pragma unroll 4
        for (int i = tid; i < 1024 * 16; i += 256) {
            int r = i >> 4, c4 = (i & 15) << 2;
            float4 v = *(float4*)&Og[(size_t)r * D_ + c4];
            v.x *= f; v.y *= f; v.z *= f; v.w *= f;
            *(float4*)&Og[(size_t)r * D_ + c4] = v;
        }
    }
}

// ---------------- launch ----------------
extern "C" void kernel_launch(void* const* d_in, const int* in_sizes, int n_in,
                              void* d_out, int out_size) {
    const float* x = (const float*)d_in[0];
    const float* Wk = (const float*)d_in[1];
    const float* bk = (const float*)d_in[2];
    const float* Wq = (const float*)d_in[3];
    const float* bq = (const float*)d_in[4];
    const float* Wv = (const float*)d_in[5];
    const float* bv = (const float*)d_in[6];
    const float* mask1 = (const float*)d_in[7];
    const float* mask2 = (const float*)d_in[8];
    const int* rb = (const int*)d_in[9];
    float* out = (float*)d_out;

    static cudaStream_t s_side = nullptr;
    static cudaEvent_t ev_fork = nullptr, ev_w = nullptr, ev_join = nullptr;
    static bool init_done = false;
    if (!init_done) {
        cudaFuncSetAttribute(attn_kernel, cudaFuncAttributeMaxDynamicSharedMemorySize,
                             ATT_SMEM_BYTES);
        cudaStreamCreateWithFlags(&s_side, cudaStreamNonBlocking);
        cudaEventCreateWithFlags(&ev_fork, cudaEventDisableTiming);
        cudaEventCreateWithFlags(&ev_w, cudaEventDisableTiming);
        cudaEventCreateWithFlags(&ev_join, cudaEventDisableTiming);
        init_done = true;
    }

    // fork: side stream does W prep (needed by proj) then mask pipeline (needed by attn)
    cudaEventRecord(ev_fork, 0);
    cudaStreamWaitEvent(s_side, ev_fork, 0);
    prep_wf<<<dim3((128 * 64 * 32) / 256, 3), 256, 0, s_side>>>(Wq, Wk, Wv);
    cudaEventRecord(ev_w, s_side);
    lm_kernel<<<dim3(S_ / 64, S_ / 64, M_), 256, 0, s_side>>>(mask1, mask2);
    gather_kernel<<<(M_ * S_ * S_) / 1024, 256, 0, s_side>>>(rb);
    cudaEventRecord(ev_join, s_side);

    // main stream: X prep runs concurrently with W prep
    prep_xf<<<(256 * 64 * 32) / 256, 256>>>(x);
    cudaStreamWaitEvent(0, ev_w, 0);  // proj needs both preps
    dim3 pgrid(D_ / 128, (B_ * S_) / 128, 3);  // (8, 32, 3)
    proj_kernel<<<pgrid, 256>>>(bq, bk, bv);

    // join: attn needs g_gath + g_ssq/g_cnt from side stream
    cudaStreamWaitEvent(0, ev_join, 0);
    attn_kernel<<<dim3(S_ / 128, B_ * H_), 256, ATT_SMEM_BYTES>>>(out);
}

// round 15
// speedup vs baseline: 1.5835x; 1.5835x over previous
#include <cuda_runtime.h>
#include <cuda_bf16.h>
#include <math.h>
#include <stdint.h>

#define B_ 4
#define S_ 1024
#define D_ 1024
#define H_ 16
#define M_ 4
#define R_ 64
#define DH_ 64
#define EPS_ 1e-8f

// ---------------- scratch (static device globals; no allocation) ----------------
__device__ __align__(16) float g_q[B_ * S_ * D_];
__device__ __align__(16) float g_k[B_ * S_ * D_];
__device__ __align__(16) float g_v[B_ * S_ * D_];
__device__ __align__(16) float g_lm[M_ * S_ * S_];
__device__ __align__(16) float g_gath[M_ * S_ * S_];
__device__ __align__(16) float g_ssq[B_ * H_];
// FRAGMENT-MAJOR packed bf16x2 hi/lo operands for proj.
__device__ __align__(16) uint32_t g_xh[B_ * S_ * (D_ / 2)];
__device__ __align__(16) uint32_t g_xl[B_ * S_ * (D_ / 2)];
__device__ __align__(16) uint32_t g_wh[3 * D_ * (D_ / 2)];
__device__ __align__(16) uint32_t g_wl[3 * D_ * (D_ / 2)];

// ---------------- helpers ----------------
__device__ __forceinline__ uint32_t f2tf(float x) {
    uint32_t u;
    asm("cvt.rna.tf32.f32 %0, %1;" : "=r"(u) : "f"(x));
    return u;
}
__device__ __forceinline__ float tfbit(float x) { return __uint_as_float(f2tf(x)); }

__device__ __forceinline__ void mma8(float d[4], const uint32_t a[4], const uint32_t b[2]) {
    asm volatile(
        "mma.sync.aligned.m16n8k8.row.col.f32.tf32.tf32.f32 "
        "{%0,%1,%2,%3},{%4,%5,%6,%7},{%8,%9},{%0,%1,%2,%3};"
        : "+f"(d[0]), "+f"(d[1]), "+f"(d[2]), "+f"(d[3])
        : "r"(a[0]), "r"(a[1]), "r"(a[2]), "r"(a[3]), "r"(b[0]), "r"(b[1]));
}

__device__ __forceinline__ void mma16(float d[4], const uint32_t a[4], const uint32_t b[2]) {
    asm volatile(
        "mma.sync.aligned.m16n8k16.row.col.f32.bf16.bf16.f32 "
        "{%0,%1,%2,%3},{%4,%5,%6,%7},{%8,%9},{%0,%1,%2,%3};"
        : "+f"(d[0]), "+f"(d[1]), "+f"(d[2]), "+f"(d[3])
        : "r"(a[0]), "r"(a[1]), "r"(a[2]), "r"(a[3]), "r"(b[0]), "r"(b[1]));
}

__device__ __forceinline__ uint32_t bf2bits(__nv_bfloat162 h) {
    return *(uint32_t*)&h;
}

__device__ __forceinline__ void cpa16(void* dst, const void* src) {
    uint32_t d = (uint32_t)__cvta_generic_to_shared(dst);
    asm volatile("cp.async.cg.shared.global [%0], [%1], 16;" :: "r"(d), "l"(src));
}

// split float2 -> packed bf16x2 hi + lo
__device__ __forceinline__ void split2(float2 f, uint32_t& hi, uint32_t& lo) {
    __nv_bfloat162 h = __floats2bfloat162_rn(f.x, f.y);
    float2 hf = __bfloat1622float2(h);
    __nv_bfloat162 l = __floats2bfloat162_rn(f.x - hf.x, f.y - hf.y);
    hi = bf2bits(h);
    lo = bf2bits(l);
}

// ---------------- prep: fp32 -> fragment-major bf16x2 hi/lo ----------------
__global__ __launch_bounds__(256) void prep_xf(const float* __restrict__ X) {
    int id = blockIdx.x * 256 + threadIdx.x;  // 524288 ids
    int l = id & 31;
    int c = (id >> 5) & 63;
    int g = id >> 11;
    int rr = l >> 2, jj = l & 3;
    const float* r0 = X + (size_t)(g * 16 + rr) * D_ + c * 16 + jj * 2;
    const float* r1 = r0 + 8 * D_;
    float2 f0 = *(const float2*)r0;
    float2 f1 = *(const float2*)r1;
    float2 f2 = *(const float2*)(r0 + 8);
    float2 f3 = *(const float2*)(r1 + 8);
    uint4 hi, lo;
    split2(f0, hi.x, lo.x);
    split2(f1, hi.y, lo.y);
    split2(f2, hi.z, lo.z);
    split2(f3, hi.w, lo.w);
    *(uint4*)&g_xh[(size_t)id * 4] = hi;
    *(uint4*)&g_xl[(size_t)id * 4] = lo;
}

__global__ __launch_bounds__(256) void prep_wf(const float* __restrict__ q,
                                               const float* __restrict__ k,
                                               const float* __restrict__ v) {
    int z = blockIdx.y;
    const float* W = (z == 0) ? q : (z == 1) ? k : v;
    size_t zoff = (size_t)z * D_ * (D_ / 2);
    int id = blockIdx.x * 256 + threadIdx.x;  // 262144 ids
    int l = id & 31;
    int c = (id >> 5) & 63;
    int gN = id >> 11;
    int rr = l >> 2, jj = l & 3;
    const float* w0 = W + (size_t)(gN * 8 + rr) * D_ + c * 16 + jj * 2;
    float2 f0 = *(const float2*)w0;
    float2 f1 = *(const float2*)(w0 + 8);
    uint2 hi, lo;
    split2(f0, hi.x, lo.x);
    split2(f1, hi.y, lo.y);
    *(uint2*)&g_wh[zoff + (size_t)id * 2] = hi;
    *(uint2*)&g_wl[zoff + (size_t)id * 2] = lo;
}

// ---------------- projection GEMM (bf16x3, smem-free, fragment LDG) ----------------
// grid (8, 32, 3); 256 threads, warps 4(m) x 2(n), warp tile 32x64.
// Outputs rounded to tf32 bit patterns (attn consumes as tf32).
__global__ __launch_bounds__(256, 2) void proj_kernel(const float* __restrict__ bq,
                                                      const float* __restrict__ bk,
                                                      const float* __restrict__ bv) {
    const int z = blockIdx.z;
    const float* bias = (z == 0) ? bq : (z == 1) ? bk : bv;
    float* Y = (z == 0) ? g_q : (z == 1) ? g_k : g_v;

    const uint4* fah = (const uint4*)g_xh;
    const uint4* fal = (const uint4*)g_xl;
    const uint2* fbh = (const uint2*)(g_wh + (size_t)z * D_ * (D_ / 2));
    const uint2* fbl = (const uint2*)(g_wl + (size_t)z * D_ * (D_ / 2));

    const int tid = threadIdx.x;
    const int warp = tid >> 5, lane = tid & 31;
    const int gid = lane >> 2, tig = lane & 3;
    const int wm = warp >> 1, wn = warp & 1;
    const int gm0 = blockIdx.y * 8 + wm * 2;
    const int gn0 = blockIdx.x * 16 + wn * 8;

    float acc[2][8][4];
#pragma unroll
    for (int mt = 0; mt < 2; mt++)
#pragma unroll
        for (int nt = 0; nt < 8; nt++)
#pragma unroll
            for (int r = 0; r < 4; r++) acc[mt][nt][r] = 0.f;

#pragma unroll 2
    for (int c = 0; c < 64; c++) {
        uint4 ah[2], al[2];
        ah[0] = fah[((size_t)gm0 * 64 + c) * 32 + lane];
        ah[1] = fah[((size_t)(gm0 + 1) * 64 + c) * 32 + lane];
        al[0] = fal[((size_t)gm0 * 64 + c) * 32 + lane];
        al[1] = fal[((size_t)(gm0 + 1) * 64 + c) * 32 + lane];
#pragma unroll
        for (int nt = 0; nt < 8; nt++) {
            uint2 bh2 = fbh[((size_t)(gn0 + nt) * 64 + c) * 32 + lane];
            uint2 bl2 = fbl[((size_t)(gn0 + nt) * 64 + c) * 32 + lane];
            uint32_t bh[2] = {bh2.x, bh2.y};
            uint32_t bl[2] = {bl2.x, bl2.y};
#pragma unroll
            for (int mt = 0; mt < 2; mt++) {
                mma16(acc[mt][nt], (const uint32_t*)&ah[mt], bh);
                mma16(acc[mt][nt], (const uint32_t*)&al[mt], bh);
                mma16(acc[mt][nt], (const uint32_t*)&ah[mt], bl);
            }
        }
    }
    const int row0 = blockIdx.y * 128;
    const int col0 = blockIdx.x * 128;
#pragma unroll
    for (int mt = 0; mt < 2; mt++) {
        int rg = row0 + wm * 32 + mt * 16 + gid;
#pragma unroll
        for (int nt = 0; nt < 8; nt++) {
            int cg = col0 + wn * 64 + nt * 8 + 2 * tig;
            float bx = bias[cg], by = bias[cg + 1];
            *(float2*)&Y[(size_t)rg * D_ + cg] =
                make_float2(tfbit(acc[mt][nt][0] + bx), tfbit(acc[mt][nt][1] + by));
            *(float2*)&Y[(size_t)(rg + 8) * D_ + cg] =
                make_float2(tfbit(acc[mt][nt][2] + bx), tfbit(acc[mt][nt][3] + by));
        }
    }
}

// ---------------- lm[m,s,t] = sum_r mask1[m,r,s] * mask2[m,r,t] (fp32) ----------------
__global__ __launch_bounds__(256) void lm_kernel(const float* __restrict__ m1,
                                                 const float* __restrict__ m2) {
    __shared__ float As[16][64];
    __shared__ float Bs[16][64];
    const int m = blockIdx.z;
    const int s0 = blockIdx.y * 64, t0 = blockIdx.x * 64;
    const int tid = threadIdx.x;
    const int tx = tid & 15, ty = tid >> 4;
    float acc[4][4];
#pragma unroll
    for (int i = 0; i < 4; i++)
#pragma unroll
        for (int j = 0; j < 4; j++) acc[i][j] = 0.f;

    for (int r0 = 0; r0 < R_; r0 += 16) {
        int rr = tid >> 4, cc = (tid & 15) << 2;
        *(float4*)&As[rr][cc] = *(const float4*)&m1[(size_t)((m * R_ + r0 + rr)) * S_ + s0 + cc];
        *(float4*)&Bs[rr][cc] = *(const float4*)&m2[(size_t)((m * R_ + r0 + rr)) * S_ + t0 + cc];
        __syncthreads();
#pragma unroll
        for (int r = 0; r < 16; r++) {
            float a[4], bb[4];
#pragma unroll
            for (int i = 0; i < 4; i++) a[i] = As[r][ty * 4 + i];
#pragma unroll
            for (int j = 0; j < 4; j++) bb[j] = Bs[r][tx + 16 * j];
#pragma unroll
            for (int i = 0; i < 4; i++)
#pragma unroll
                for (int j = 0; j < 4; j++) acc[i][j] += a[i] * bb[j];
        }
        __syncthreads();
    }
#pragma unroll
    for (int i = 0; i < 4; i++)
#pragma unroll
        for (int j = 0; j < 4; j++)
            g_lm[(size_t)(m * S_ + s0 + ty * 4 + i) * S_ + t0 + tx + 16 * j] = acc[i][j];
}

// ---------------- gathered[m,s,t] = lm[m,s,rb[m,s,t]]  (+ zero ssq) ----------------
__global__ __launch_bounds__(256) void gather_kernel(const int* __restrict__ rb) {
    if (blockIdx.x == 0 && threadIdx.x < B_ * H_) g_ssq[threadIdx.x] = 0.f;
    int i4 = (blockIdx.x * 256 + threadIdx.x) * 4;  // over M*S*S
    int row = i4 >> 10;                             // combined (m*S + s)
    const float* lrow = &g_lm[(size_t)row << 10];
    int4 u = *(const int4*)&rb[i4];
    g_gath[i4 + 0] = lrow[u.x & (S_ - 1)];
    g_gath[i4 + 1] = lrow[u.y & (S_ - 1)];
    g_gath[i4 + 2] = lrow[u.z & (S_ - 1)];
    g_gath[i4 + 3] = lrow[u.w & (S_ - 1)];
}

// ---------------- fused attention (cp.async double-buffered 64-row t-tiles) ----------------
// grid (S/128, B*H), 256 thr (8 warps, warp tile m=16). q/k/v already tf32-rounded.
#define KSTRIDE 76
#define VSTRIDE 72
#define ATT_BUF_FLOATS (64 * KSTRIDE + 64 * VSTRIDE)
#define ATT_SMEM_BYTES (2 * ATT_BUF_FLOATS * 4)

__global__ __launch_bounds__(256, 2) void attn_kernel(float* __restrict__ out) {
    extern __shared__ float sm[];

    const int tid = threadIdx.x, warp = tid >> 5, lane = tid & 31;
    const int gid = lane >> 2, tig = lane & 3;
    const int bh = blockIdx.y;
    const int b = bh >> 4, h = bh & 15;
    const int midx = h & 3;
    const int s0 = blockIdx.x * 128;
    const int mrow = warp * 16;

    const float* Qg = g_q + (size_t)b * S_ * D_ + h * 64;
    const float* Kg = g_k + (size_t)b * S_ * D_ + h * 64;
    const float* Vg = g_v + (size_t)b * S_ * D_ + h * 64;
    const float* grow = g_gath + (size_t)midx * S_ * S_;

    // Q fragments direct from gmem (values are tf32 bit patterns already)
    uint32_t qf[8][4];
    {
        const float* Qr0 = &Qg[(size_t)(s0 + mrow + gid) * D_];
        const float* Qr1 = &Qg[(size_t)(s0 + mrow + gid + 8) * D_];
#pragma unroll
        for (int kc = 0; kc < 8; kc++) {
            qf[kc][0] = __float_as_uint(Qr0[kc * 8 + tig]);
            qf[kc][1] = __float_as_uint(Qr1[kc * 8 + tig]);
            qf[kc][2] = __float_as_uint(Qr0[kc * 8 + tig + 4]);
            qf[kc][3] = __float_as_uint(Qr1[kc * 8 + tig + 4]);
        }
    }

    float oacc[8][4];
#pragma unroll
    for (int nt = 0; nt < 8; nt++)
#pragma unroll
        for (int r = 0; r < 4; r++) oacc[nt][r] = 0.f;
    float ssq = 0.f;

    const int srcA = (lane & ~3) | (tig >> 1);
    const int srcB = srcA + 2;
    const bool odd = (tig & 1);

    auto stage = [&](int tt) {
        const int t0 = tt * 64;
        float* base = sm + (tt & 1) * ATT_BUF_FLOATS;
#pragma unroll
        for (int t = 0; t < 4; t++) {
            int id = tid + t * 256;
            int r = id >> 4, c = (id & 15) << 2;
            cpa16(&base[r * KSTRIDE + c], &Kg[(size_t)(t0 + r) * D_ + c]);
            cpa16(&base[64 * KSTRIDE + r * VSTRIDE + c], &Vg[(size_t)(t0 + r) * D_ + c]);
        }
        asm volatile("cp.async.commit_group;");
    };

    stage(0);

    for (int tt = 0; tt < 16; tt++) {
        if (tt < 15) {
            stage(tt + 1);
            asm volatile("cp.async.wait_group 1;");
        } else {
            asm volatile("cp.async.wait_group 0;");
        }
        __syncthreads();

        const float* Ks = sm + (tt & 1) * ATT_BUF_FLOATS;
        const float* Vs = Ks + 64 * KSTRIDE;
        const int t0 = tt * 64;

#pragma unroll
        for (int nt = 0; nt < 8; nt++) {
            float p[4] = {0.f, 0.f, 0.f, 0.f};
#pragma unroll
            for (int kc = 0; kc < 8; kc++) {
                uint32_t bf[2];
                bf[0] = __float_as_uint(Ks[(nt * 8 + gid) * KSTRIDE + kc * 8 + tig]);
                bf[1] = __float_as_uint(Ks[(nt * 8 + gid) * KSTRIDE + kc * 8 + tig + 4]);
                mma8(p, qf[kc], bf);
            }
            int srow = s0 + mrow + gid;
            int tcol = t0 + nt * 8 + 2 * tig;
            float2 g0 = *(const float2*)&grow[(size_t)srow * S_ + tcol];
            float2 g1 = *(const float2*)&grow[(size_t)(srow + 8) * S_ + tcol];
            float v0 = p[0] * 0.125f * g0.x;
            float v1 = p[1] * 0.125f * g0.y;
            float v2 = p[2] * 0.125f * g1.x;
            float v3 = p[3] * 0.125f * g1.y;
            ssq += v0 * v0 + v1 * v1 + v2 * v2 + v3 * v3;
            float c0 = tfbit(v0), c1 = tfbit(v1), c2 = tfbit(v2), c3 = tfbit(v3);
            float w00 = __shfl_sync(0xffffffffu, c0, srcA);
            float w01 = __shfl_sync(0xffffffffu, c1, srcA);
            float w10 = __shfl_sync(0xffffffffu, c2, srcA);
            float w11 = __shfl_sync(0xffffffffu, c3, srcA);
            float w20 = __shfl_sync(0xffffffffu, c0, srcB);
            float w21 = __shfl_sync(0xffffffffu, c1, srcB);
            float w30 = __shfl_sync(0xffffffffu, c2, srcB);
            float w31 = __shfl_sync(0xffffffffu, c3, srcB);
            uint32_t af[4];
            af[0] = __float_as_uint(odd ? w01 : w00);
            af[1] = __float_as_uint(odd ? w11 : w10);
            af[2] = __float_as_uint(odd ? w21 : w20);
            af[3] = __float_as_uint(odd ? w31 : w30);
#pragma unroll
            for (int vn = 0; vn < 8; vn++) {
                uint32_t bf[2];
                bf[0] = __float_as_uint(Vs[(nt * 8 + tig) * VSTRIDE + vn * 8 + gid]);
                bf[1] = __float_as_uint(Vs[(nt * 8 + tig + 4) * VSTRIDE + vn * 8 + gid]);
                mma8(oacc[vn], af, bf);
            }
        }
        __syncthreads();
    }

    float* Og = out + (size_t)b * S_ * D_ + h * 64;
    const int srow = s0 + mrow + gid;
#pragma unroll
    for (int nt = 0; nt < 8; nt++) {
        int c = nt * 8 + 2 * tig;
        *(float2*)&Og[(size_t)srow * D_ + c] = make_float2(oacc[nt][0], oacc[nt][1]);
        *(float2*)&Og[(size_t)(srow + 8) * D_ + c] = make_float2(oacc[nt][2], oacc[nt][3]);
    }
#pragma unroll
    for (int off = 16; off; off >>= 1) ssq += __shfl_xor_sync(0xffffffffu, ssq, off);
    if (lane == 0) atomicAdd(&g_ssq[bh], ssq);
}

// ---------------- final scale by 1/(||att||_F + eps) ----------------
__global__ __launch_bounds__(256) void scale_kernel(float* __restrict__ out) {
    int i4 = (blockIdx.x * 256 + threadIdx.x) * 4;  // over B*S*D
    int col = i4 & (D_ - 1);
    int h = col >> 6;
    int b = i4 >> 20;  // / (S_*D_)
    float f = 1.f / (sqrtf(g_ssq[b * H_ + h]) + EPS_);
    float4 v = *(float4*)&out[i4];
    v.x *= f; v.y *= f; v.z *= f; v.w *= f;
    *(float4*)&out[i4] = v;
}

// ---------------- launch ----------------
extern "C" void kernel_launch(void* const* d_in, const int* in_sizes, int n_in,
                              void* d_out, int out_size) {
    const float* x = (const float*)d_in[0];
    const float* Wk = (const float*)d_in[1];
    const float* bk = (const float*)d_in[2];
    const float* Wq = (const float*)d_in[3];
    const float* bq = (const float*)d_in[4];
    const float* Wv = (const float*)d_in[5];
    const float* bv = (const float*)d_in[6];
    const float* mask1 = (const float*)d_in[7];
    const float* mask2 = (const float*)d_in[8];
    const int* rb = (const int*)d_in[9];
    float* out = (float*)d_out;

    static cudaStream_t s_side = nullptr;
    static cudaEvent_t ev_fork = nullptr, ev_w = nullptr, ev_join = nullptr;
    static bool init_done = false;
    if (!init_done) {
        cudaFuncSetAttribute(attn_kernel, cudaFuncAttributeMaxDynamicSharedMemorySize,
                             ATT_SMEM_BYTES);
        cudaStreamCreateWithFlags(&s_side, cudaStreamNonBlocking);
        cudaEventCreateWithFlags(&ev_fork, cudaEventDisableTiming);
        cudaEventCreateWithFlags(&ev_w, cudaEventDisableTiming);
        cudaEventCreateWithFlags(&ev_join, cudaEventDisableTiming);
        init_done = true;
    }

    // fork: side stream does W prep (needed by proj) then mask pipeline (needed by attn)
    cudaEventRecord(ev_fork, 0);
    cudaStreamWaitEvent(s_side, ev_fork, 0);
    prep_wf<<<dim3((128 * 64 * 32) / 256, 3), 256, 0, s_side>>>(Wq, Wk, Wv);
    cudaEventRecord(ev_w, s_side);
    lm_kernel<<<dim3(S_ / 64, S_ / 64, M_), 256, 0, s_side>>>(mask1, mask2);
    gather_kernel<<<(M_ * S_ * S_) / 1024, 256, 0, s_side>>>(rb);
    cudaEventRecord(ev_join, s_side);

    // main stream: X prep runs concurrently with W prep
    prep_xf<<<(256 * 64 * 32) / 256, 256>>>(x);
    cudaStreamWaitEvent(0, ev_w, 0);  // proj needs both preps
    dim3 pgrid(D_ / 128, (B_ * S_) / 128, 3);  // (8, 32, 3)
    proj_kernel<<<pgrid, 256>>>(bq, bk, bv);

    // join: attn needs g_gath + g_ssq from side stream
    cudaStreamWaitEvent(0, ev_join, 0);
    attn_kernel<<<dim3(S_ / 128, B_ * H_), 256, ATT_SMEM_BYTES>>>(out);

    scale_kernel<<<(B_ * S_ * D_) / 1024, 256>>>(out);
}